// round 12
// baseline (speedup 1.0000x reference)
#include <cuda_runtime.h>
#include <math.h>

// Problem constants
#define BATCH 16
#define CIN   16
#define HH    224
#define WW    224
#define hh    112
#define ww    112
#define NTOK  12544        // 112*112
#define C1    72           // (16+2)*4
#define CHN   18           // 16+2
#define MS    256          // samples
#define KNB   3

typedef unsigned long long ull;
#define PACK2(d, lo, hi)   asm("mov.b64 %0, {%1, %2};" : "=l"(d) : "f"(lo), "f"(hi))
#define UNPACK2(lo, hi, s) asm("mov.b64 {%0, %1}, %2;" : "=f"(lo), "=f"(hi) : "l"(s))
#define FMA2(d, a, b, c)   asm("fma.rn.f32x2 %0, %1, %2, %3;" : "=l"(d) : "l"(a), "l"(b), "l"(c))

// Scratch (static __device__ -> .bss, no allocations)
__device__ __align__(16) float g_x1t[(size_t)BATCH*NTOK*C1];   // token-major unshuffled input (+coords)
__device__ __align__(16) float g_ys [(size_t)BATCH*MS*C1];     // normalized sample vectors
__device__            int   g_nbr[(size_t)BATCH*NTOK*KNB];     // top-3 neighbor SAMPLE indices (0..255)
__device__ __align__(16) float g_T  [(size_t)BATCH*KNB*MS*C1]; // T[b][k][m][o]: conv-transformed samples

// round(linspace(0,111,16)) — verified against f32 linspace rounding
__constant__ int c_SIDX[16] = {0,7,15,22,30,37,44,52,59,67,74,81,89,96,104,111};

// ---------------------------------------------------------------------------
// K1: coords + pixel-unshuffle into token-major layout.
// ---------------------------------------------------------------------------
__global__ __launch_bounds__(256) void k1_build(const float* __restrict__ x) {
    int idx = blockIdx.x * 256 + threadIdx.x;      // b*NTOK + n, exact grid
    int b = idx / NTOK, n = idx % NTOK;
    int i = n / ww, j = n % ww;
    const float* xb = x + (size_t)b * CIN * HH * WW;
    float row[C1];
#pragma unroll
    for (int ch = 0; ch < CIN; ch++) {
#pragma unroll
        for (int s1 = 0; s1 < 2; s1++) {
            float2 v = *(const float2*)(xb + ((size_t)ch * HH + (2*i + s1)) * WW + 2*j);
            row[ch*4 + s1*2 + 0] = v.x;
            row[ch*4 + s1*2 + 1] = v.y;
        }
    }
#pragma unroll
    for (int s1 = 0; s1 < 2; s1++)
#pragma unroll
        for (int s2 = 0; s2 < 2; s2++) {
            float p = (float)(2*i + s1), q = (float)(2*j + s2);
            float r = sqrtf(__fadd_rn(__fmul_rn(p, p), __fmul_rn(q, q)));  // exact ints
            float rm = fmaxf(r, 1e-12f);
            row[64 + s1*2 + s2] = __fdiv_rn(p, rm);   // channel 16 block
            row[68 + s1*2 + s2] = __fdiv_rn(q, rm);   // channel 17 block
        }
    float4* dst = (float4*)(g_x1t + (size_t)idx * C1);
#pragma unroll
    for (int c = 0; c < C1/4; c++)
        dst[c] = make_float4(row[4*c], row[4*c+1], row[4*c+2], row[4*c+3]);
}

// ---------------------------------------------------------------------------
// K2: gather + L2-normalize the 256 sampled vectors per batch.
// ---------------------------------------------------------------------------
__global__ void k2_samples() {
    int idx = blockIdx.x * blockDim.x + threadIdx.x;   // b*256 + m
    if (idx >= BATCH * MS) return;
    int b = idx >> 8, m = idx & 255;
    int tok = c_SIDX[m >> 4] * ww + c_SIDX[m & 15];
    const float4* src = (const float4*)(g_x1t + ((size_t)b * NTOK + tok) * C1);
    float v[C1];
#pragma unroll
    for (int c = 0; c < 18; c++) {
        float4 t = src[c];
        v[4*c] = t.x; v[4*c+1] = t.y; v[4*c+2] = t.z; v[4*c+3] = t.w;
    }
    float ss = 0.f;
#pragma unroll
    for (int c = 0; c < C1; c++) ss = __fmaf_rn(v[c], v[c], ss);
    float nrm = fmaxf(sqrtf(ss), 1e-12f);
    float4* dst = (float4*)(g_ys + (size_t)idx * C1);
#pragma unroll
    for (int c = 0; c < 18; c++)
        dst[c] = make_float4(__fdiv_rn(v[4*c],   nrm), __fdiv_rn(v[4*c+1], nrm),
                             __fdiv_rn(v[4*c+2], nrm), __fdiv_rn(v[4*c+3], nrm));
}

// ---------------------------------------------------------------------------
// K3: cosine sim + top-3.
// Pass 1 (CANDIDATE COLLECTOR): packed f32x2 FMA chains (2x issue density)
//        stream top-6 candidates. Association differs from asc-FMA -> only
//        used to pick candidates, never for final order.
// Pass 2: re-score the 6 candidates with the strict ascending-FMA chain and
//        rank via ascending-index streaming insertion (bit-identical to the
//        R10 passing semantics), then compensated-dot sub-ulp tie repair
//        (jax.lax.top_k lower-index-first) on the ranked top-4.
// ---------------------------------------------------------------------------
#define EPS_ULP 6.0e-8
__global__ __launch_bounds__(256) void k3_sim() {
    extern __shared__ float ys[];
    int b = blockIdx.y;
    int n = blockIdx.x * 256 + threadIdx.x;
    {
        const float4* src = (const float4*)(g_ys + (size_t)b * MS * C1);
        float4* d = (float4*)ys;
        for (int t = threadIdx.x; t < MS * C1 / 4; t += 256) d[t] = src[t];
    }
    __syncthreads();

    // normalized token vector, packed into 36 f32x2 pairs
    ull v2[C1/2];
    {
        float vr[C1];
        const float4* src = (const float4*)(g_x1t + ((size_t)b * NTOK + n) * C1);
#pragma unroll
        for (int c = 0; c < 18; c++) {
            float4 t = src[c];
            vr[4*c] = t.x; vr[4*c+1] = t.y; vr[4*c+2] = t.z; vr[4*c+3] = t.w;
        }
        float ss = 0.f;
#pragma unroll
        for (int c = 0; c < C1; c++) ss = __fmaf_rn(vr[c], vr[c], ss);
        float nrm = fmaxf(sqrtf(ss), 1e-12f);
#pragma unroll
        for (int p = 0; p < C1/2; p++) {
            float d0 = __fdiv_rn(vr[2*p],   nrm);
            float d1 = __fdiv_rn(vr[2*p+1], nrm);
            PACK2(v2[p], d0, d1);
        }
    }

    // ---- pass 1: packed-FMA sims, streaming top-6 candidates ----
    float tv[6]; int ti[6];
#pragma unroll
    for (int t = 0; t < 6; t++) { tv[t] = -1e30f; ti[t] = 0; }
    for (int m0 = 0; m0 < MS; m0 += 4) {
        ull a0 = 0, a1 = 0, a2 = 0, a3 = 0;   // (0.0f,0.0f) packed
        const ulonglong2* y0 = (const ulonglong2*)(ys + (m0 + 0) * C1);
        const ulonglong2* y1 = (const ulonglong2*)(ys + (m0 + 1) * C1);
        const ulonglong2* y2 = (const ulonglong2*)(ys + (m0 + 2) * C1);
        const ulonglong2* y3 = (const ulonglong2*)(ys + (m0 + 3) * C1);
#pragma unroll
        for (int c = 0; c < 18; c++) {        // 4 floats = 2 packed pairs per row
            ulonglong2 u0 = y0[c], u1 = y1[c], u2 = y2[c], u3 = y3[c];
            FMA2(a0, v2[2*c],   u0.x, a0);
            FMA2(a1, v2[2*c],   u1.x, a1);
            FMA2(a2, v2[2*c],   u2.x, a2);
            FMA2(a3, v2[2*c],   u3.x, a3);
            FMA2(a0, v2[2*c+1], u0.y, a0);
            FMA2(a1, v2[2*c+1], u1.y, a1);
            FMA2(a2, v2[2*c+1], u2.y, a2);
            FMA2(a3, v2[2*c+1], u3.y, a3);
        }
        float sv[4];
        { float lo, hi; UNPACK2(lo, hi, a0); sv[0] = lo + hi;
          UNPACK2(lo, hi, a1); sv[1] = lo + hi;
          UNPACK2(lo, hi, a2); sv[2] = lo + hi;
          UNPACK2(lo, hi, a3); sv[3] = lo + hi; }
#pragma unroll
        for (int d = 0; d < 4; d++) {
            float s = sv[d]; int m = m0 + d;
            if (s > tv[5]) {
                if (s > tv[0])      { tv[5]=tv[4];ti[5]=ti[4]; tv[4]=tv[3];ti[4]=ti[3]; tv[3]=tv[2];ti[3]=ti[2]; tv[2]=tv[1];ti[2]=ti[1]; tv[1]=tv[0];ti[1]=ti[0]; tv[0]=s;ti[0]=m; }
                else if (s > tv[1]) { tv[5]=tv[4];ti[5]=ti[4]; tv[4]=tv[3];ti[4]=ti[3]; tv[3]=tv[2];ti[3]=ti[2]; tv[2]=tv[1];ti[2]=ti[1]; tv[1]=s;ti[1]=m; }
                else if (s > tv[2]) { tv[5]=tv[4];ti[5]=ti[4]; tv[4]=tv[3];ti[4]=ti[3]; tv[3]=tv[2];ti[3]=ti[2]; tv[2]=s;ti[2]=m; }
                else if (s > tv[3]) { tv[5]=tv[4];ti[5]=ti[4]; tv[4]=tv[3];ti[4]=ti[3]; tv[3]=s;ti[3]=m; }
                else if (s > tv[4]) { tv[5]=tv[4];ti[5]=ti[4]; tv[4]=s;ti[4]=m; }
                else                { tv[5]=s;ti[5]=m; }
            }
        }
    }

    // unpack v2 -> scalar v (v2 dead after; ranges barely overlap)
    float v[C1];
#pragma unroll
    for (int p = 0; p < C1/2; p++) UNPACK2(v[2*p], v[2*p+1], v2[p]);

    // sort candidate indices ascending (stable streaming insertion below)
    int cm[6];
#pragma unroll
    for (int t = 0; t < 6; t++) cm[t] = ti[t];
#pragma unroll
    for (int a = 1; a < 6; a++) {
        int key = cm[a]; int p = a - 1;
        while (p >= 0 && cm[p] > key) { cm[p+1] = cm[p]; p--; }
        cm[p+1] = key;
    }

    // ---- pass 2a: asc-FMA re-score + streaming top-4 (R10 semantics) ----
    float v0 = -1e30f, v1 = -1e30f, v2f = -1e30f, v3 = -1e30f;
    int   i0 = 0, i1 = 0, i2 = 0, i3 = 0;
#pragma unroll
    for (int t = 0; t < 6; t++) {
        const float* y = ys + cm[t] * C1;
        float s = 0.f;
#pragma unroll
        for (int k = 0; k < C1; k++) s = __fmaf_rn(v[k], y[k], s);
        int m = cm[t];
        if (s > v0)       { v3=v2f;i3=i2; v2f=v1;i2=i1; v1=v0;i1=i0; v0=s;i0=m; }
        else if (s > v1)  { v3=v2f;i3=i2; v2f=v1;i2=i1; v1=s;i1=m; }
        else if (s > v2f) { v3=v2f;i3=i2; v2f=s;i2=m; }
        else if (s > v3)  { v3=s;i3=m; }
    }

    // ---- pass 2b: compensated-exact sims + sub-ulp tie repair ----
    int   ci[4] = {i0, i1, i2, i3};
    double ex[4];
#pragma unroll
    for (int t = 0; t < 4; t++) {
        const float* y = ys + ci[t] * C1;
        float s = 0.f, comp = 0.f;
#pragma unroll
        for (int k = 0; k < C1; k++) {
            float a = v[k], bb = y[k];
            float p  = __fmul_rn(a, bb);
            float e  = __fmaf_rn(a, bb, -p);           // exact product tail
            float tt = s + p;
            float z  = (fabsf(s) >= fabsf(p)) ? ((s - tt) + p) : ((p - tt) + s);
            s = tt;
            comp = comp + (z + e);
        }
        ex[t] = (double)s + (double)comp;
    }
#pragma unroll
    for (int p = 0; p < 3; p++) {
#pragma unroll
        for (int q = 0; q < 3 - p; q++) {
            if (fabs(ex[q] - ex[q+1]) <= EPS_ULP && ci[q] > ci[q+1]) {
                double td = ex[q]; ex[q] = ex[q+1]; ex[q+1] = td;
                int    tm = ci[q]; ci[q] = ci[q+1]; ci[q+1] = tm;
            }
        }
    }

    int* nb = g_nbr + ((size_t)b * NTOK + n) * 3;
    nb[0] = ci[0];   // sample index, consumed by k5_fused via g_T
    nb[1] = ci[1];
    nb[2] = ci[2];
}

// ---------------------------------------------------------------------------
// KT: conv factorization, now chip-wide: grid (16 batches, 9 o-chunks of 8).
// T[b][k][m][o] = sum_c w1[o][c][k] * xs[b][m][c].
// ---------------------------------------------------------------------------
#define KT_OC 8
__global__ __launch_bounds__(256) void kT_gemm(const float* __restrict__ w1) {
    __shared__ float w1s[KT_OC * 216];      // 6912 B
    int b   = blockIdx.x;
    int oc0 = blockIdx.y * KT_OC;
    for (int t = threadIdx.x; t < KT_OC * 216 / 4; t += 256)
        ((float4*)w1s)[t] = ((const float4*)(w1 + oc0 * 216))[t];
    __syncthreads();

    int m = threadIdx.x;
    int tok = c_SIDX[m >> 4] * ww + c_SIDX[m & 15];
    float xs[C1];
    {
        const float4* src = (const float4*)(g_x1t + ((size_t)b * NTOK + tok) * C1);
#pragma unroll
        for (int c = 0; c < 18; c++) {
            float4 t = src[c];
            xs[4*c] = t.x; xs[4*c+1] = t.y; xs[4*c+2] = t.z; xs[4*c+3] = t.w;
        }
    }

#pragma unroll
    for (int oo = 0; oo < KT_OC; oo++) {
        int o = oc0 + oo;
        const float4* wrow = (const float4*)(w1s + oo * 216);   // w1[o][c][k]
        float a0 = 0.f, a1 = 0.f, a2 = 0.f;
#pragma unroll
        for (int q = 0; q < 54; q++) {
            float4 wv = wrow[q];
            float we[4] = {wv.x, wv.y, wv.z, wv.w};
#pragma unroll
            for (int e = 0; e < 4; e++) {
                const int idx = 4*q + e;
                const int c = idx / 3, k = idx % 3;
                if (k == 0) a0 = __fmaf_rn(xs[c], we[e], a0);
                if (k == 1) a1 = __fmaf_rn(xs[c], we[e], a1);
                if (k == 2) a2 = __fmaf_rn(xs[c], we[e], a2);
            }
        }
        g_T[(((size_t)b*3 + 0) * MS + m) * C1 + o] = a0;
        g_T[(((size_t)b*3 + 1) * MS + m) * C1 + o] = a1;
        g_T[(((size_t)b*3 + 2) * MS + m) * C1 + o] = a2;
    }
}

// ---------------------------------------------------------------------------
// K5 (fused): sum 3 T rows + bias = conv row, then PixelShuffle + pointwise.
// ---------------------------------------------------------------------------
__global__ __launch_bounds__(256) void k5_fused(const float* __restrict__ b1,
                                                const float* __restrict__ wpw,
                                                const float* __restrict__ bpw,
                                                float* __restrict__ out) {
    __shared__ float ws[16 * 18];
    __shared__ float bs[16];
    __shared__ float b1s[C1];
    int tid = threadIdx.x;
    for (int t = tid; t < 16 * 18; t += 256) ws[t] = wpw[t];
    if (tid < 16) bs[tid] = bpw[tid];
    if (tid < C1) b1s[tid] = b1[tid];
    __syncthreads();

    int idx = blockIdx.x * 256 + tid;   // b*NTOK + n
    int b = idx / NTOK, n = idx % NTOK;
    int i = n / ww, j = n % ww;

    const int* nb = g_nbr + (size_t)idx * 3;
    const float4* t0 = (const float4*)(g_T + (((size_t)b*3 + 0) * MS + nb[0]) * C1);
    const float4* t1 = (const float4*)(g_T + (((size_t)b*3 + 1) * MS + nb[1]) * C1);
    const float4* t2 = (const float4*)(g_T + (((size_t)b*3 + 2) * MS + nb[2]) * C1);

    float row[C1];
#pragma unroll
    for (int c = 0; c < 18; c++) {
        float4 p = t0[c], q = t1[c], r = t2[c];
        row[4*c+0] = b1s[4*c+0] + p.x + q.x + r.x;
        row[4*c+1] = b1s[4*c+1] + p.y + q.y + r.y;
        row[4*c+2] = b1s[4*c+2] + p.z + q.z + r.z;
        row[4*c+3] = b1s[4*c+3] + p.w + q.w + r.w;
    }

    float* ob = out + (size_t)b * CIN * HH * WW;
#pragma unroll 4
    for (int oc = 0; oc < 16; oc++) {
#pragma unroll
        for (int s1 = 0; s1 < 2; s1++) {
            float a0 = bs[oc], a1 = bs[oc];
#pragma unroll
            for (int c = 0; c < 18; c++) {
                float wv = ws[oc * 18 + c];
                a0 = __fmaf_rn(wv, row[c*4 + s1*2 + 0], a0);
                a1 = __fmaf_rn(wv, row[c*4 + s1*2 + 1], a1);
            }
            *(float2*)(ob + ((size_t)oc * HH + (2*i + s1)) * WW + 2*j) = make_float2(a0, a1);
        }
    }
}

// ---------------------------------------------------------------------------
extern "C" void kernel_launch(void* const* d_in, const int* in_sizes, int n_in,
                              void* d_out, int out_size) {
    const float *x = nullptr, *w1 = nullptr, *b1 = nullptr, *wpw = nullptr, *bpw = nullptr;
    for (int i = 0; i < n_in; i++) {
        switch (in_sizes[i]) {
            case 12845056: x   = (const float*)d_in[i]; break;  // (16,16,224,224)
            case 15552:    w1  = (const float*)d_in[i]; break;  // (72,72,3)
            case 72:       b1  = (const float*)d_in[i]; break;  // (72,)
            case 288:      wpw = (const float*)d_in[i]; break;  // (16,18,1,1)
            case 16:       bpw = (const float*)d_in[i]; break;  // (16,)
        }
    }
    float* out = (float*)d_out;

    cudaFuncSetAttribute(k3_sim, cudaFuncAttributeMaxDynamicSharedMemorySize, 73728);

    k1_build   <<<784, 256>>>(x);                        // 16*12544/256
    k2_samples <<<16, 256>>>();
    k3_sim     <<<dim3(49, 16), 256, 73728>>>();         // 12544/256 = 49
    kT_gemm    <<<dim3(16, 9), 256>>>(w1);
    k5_fused   <<<784, 256>>>(b1, wpw, bpw, out);
}

// round 15
// speedup vs baseline: 1.1663x; 1.1663x over previous
#include <cuda_runtime.h>
#include <math.h>

// Problem constants
#define BATCH 16
#define CIN   16
#define HH    224
#define WW    224
#define hh    112
#define ww    112
#define NTOK  12544        // 112*112
#define C1    72           // (16+2)*4
#define CHN   18           // 16+2
#define MS    256          // samples
#define KNB   3

// Scratch (static __device__ -> .bss, no allocations)
__device__ __align__(16) float g_x1t[(size_t)BATCH*NTOK*C1];   // token-major unshuffled input (+coords)
__device__ __align__(16) float g_ys [(size_t)BATCH*MS*C1];     // normalized sample vectors
__device__            int   g_nbr[(size_t)BATCH*NTOK*KNB];     // top-3 neighbor SAMPLE indices (0..255)
__device__ __align__(16) float g_T  [(size_t)BATCH*KNB*MS*C1]; // T[b][k][m][o]: conv-transformed samples

// round(linspace(0,111,16)) — verified against f32 linspace rounding
__constant__ int c_SIDX[16] = {0,7,15,22,30,37,44,52,59,67,74,81,89,96,104,111};

// ---------------------------------------------------------------------------
// K1: coords + pixel-unshuffle into token-major layout.
// ---------------------------------------------------------------------------
__global__ __launch_bounds__(256) void k1_build(const float* __restrict__ x) {
    int idx = blockIdx.x * 256 + threadIdx.x;      // b*NTOK + n, exact grid
    int b = idx / NTOK, n = idx % NTOK;
    int i = n / ww, j = n % ww;
    const float* xb = x + (size_t)b * CIN * HH * WW;
    float row[C1];
#pragma unroll
    for (int ch = 0; ch < CIN; ch++) {
#pragma unroll
        for (int s1 = 0; s1 < 2; s1++) {
            float2 v = *(const float2*)(xb + ((size_t)ch * HH + (2*i + s1)) * WW + 2*j);
            row[ch*4 + s1*2 + 0] = v.x;
            row[ch*4 + s1*2 + 1] = v.y;
        }
    }
#pragma unroll
    for (int s1 = 0; s1 < 2; s1++)
#pragma unroll
        for (int s2 = 0; s2 < 2; s2++) {
            float p = (float)(2*i + s1), q = (float)(2*j + s2);
            float r = sqrtf(__fadd_rn(__fmul_rn(p, p), __fmul_rn(q, q)));  // exact ints
            float rm = fmaxf(r, 1e-12f);
            row[64 + s1*2 + s2] = __fdiv_rn(p, rm);   // channel 16 block
            row[68 + s1*2 + s2] = __fdiv_rn(q, rm);   // channel 17 block
        }
    float4* dst = (float4*)(g_x1t + (size_t)idx * C1);
#pragma unroll
    for (int c = 0; c < C1/4; c++)
        dst[c] = make_float4(row[4*c], row[4*c+1], row[4*c+2], row[4*c+3]);
}

// ---------------------------------------------------------------------------
// K2: gather + L2-normalize the 256 sampled vectors per batch.
// ---------------------------------------------------------------------------
__global__ void k2_samples() {
    int idx = blockIdx.x * blockDim.x + threadIdx.x;   // b*256 + m
    if (idx >= BATCH * MS) return;
    int b = idx >> 8, m = idx & 255;
    int tok = c_SIDX[m >> 4] * ww + c_SIDX[m & 15];
    const float4* src = (const float4*)(g_x1t + ((size_t)b * NTOK + tok) * C1);
    float v[C1];
#pragma unroll
    for (int c = 0; c < 18; c++) {
        float4 t = src[c];
        v[4*c] = t.x; v[4*c+1] = t.y; v[4*c+2] = t.z; v[4*c+3] = t.w;
    }
    float ss = 0.f;
#pragma unroll
    for (int c = 0; c < C1; c++) ss = __fmaf_rn(v[c], v[c], ss);
    float nrm = fmaxf(sqrtf(ss), 1e-12f);
    float4* dst = (float4*)(g_ys + (size_t)idx * C1);
#pragma unroll
    for (int c = 0; c < 18; c++)
        dst[c] = make_float4(__fdiv_rn(v[4*c],   nrm), __fdiv_rn(v[4*c+1], nrm),
                             __fdiv_rn(v[4*c+2], nrm), __fdiv_rn(v[4*c+3], nrm));
}

// ---------------------------------------------------------------------------
// K3: cosine sim + top-3 with sub-ulp tie repair. EXACT R10/R11 passing logic
// (scalar ascending-FMA chains; packed-f32x2 variant regressed in R12).
// ---------------------------------------------------------------------------
#define EPS_ULP 6.0e-8
__global__ __launch_bounds__(256) void k3_sim() {
    extern __shared__ float ys[];
    int b = blockIdx.y;
    int n = blockIdx.x * 256 + threadIdx.x;
    {
        const float4* src = (const float4*)(g_ys + (size_t)b * MS * C1);
        float4* d = (float4*)ys;
        for (int t = threadIdx.x; t < MS * C1 / 4; t += 256) d[t] = src[t];
    }
    __syncthreads();

    float v[C1];
    {
        const float4* src = (const float4*)(g_x1t + ((size_t)b * NTOK + n) * C1);
#pragma unroll
        for (int c = 0; c < 18; c++) {
            float4 t = src[c];
            v[4*c] = t.x; v[4*c+1] = t.y; v[4*c+2] = t.z; v[4*c+3] = t.w;
        }
        float ss = 0.f;
#pragma unroll
        for (int c = 0; c < C1; c++) ss = __fmaf_rn(v[c], v[c], ss);
        float nrm = fmaxf(sqrtf(ss), 1e-12f);
#pragma unroll
        for (int c = 0; c < C1; c++) v[c] = __fdiv_rn(v[c], nrm);
    }

    // ---- pass 1: ascending-FMA sims, streaming top-4 ----
    float v0 = -1e30f, v1 = -1e30f, v2 = -1e30f, v3 = -1e30f;
    int   i0 = 0, i1 = 0, i2 = 0, i3 = 0;
    for (int m0 = 0; m0 < MS; m0 += 4) {
        float a0 = 0.f, a1 = 0.f, a2 = 0.f, a3 = 0.f;
        const float* y0 = ys + (m0 + 0) * C1;
        const float* y1 = ys + (m0 + 1) * C1;
        const float* y2 = ys + (m0 + 2) * C1;
        const float* y3 = ys + (m0 + 3) * C1;
#pragma unroll
        for (int c = 0; c < 18; c++) {
            float4 t0 = *(const float4*)(y0 + 4*c);
            float4 t1 = *(const float4*)(y1 + 4*c);
            float4 t2 = *(const float4*)(y2 + 4*c);
            float4 t3 = *(const float4*)(y3 + 4*c);
            a0 = __fmaf_rn(v[4*c],   t0.x, a0);
            a1 = __fmaf_rn(v[4*c],   t1.x, a1);
            a2 = __fmaf_rn(v[4*c],   t2.x, a2);
            a3 = __fmaf_rn(v[4*c],   t3.x, a3);
            a0 = __fmaf_rn(v[4*c+1], t0.y, a0);
            a1 = __fmaf_rn(v[4*c+1], t1.y, a1);
            a2 = __fmaf_rn(v[4*c+1], t2.y, a2);
            a3 = __fmaf_rn(v[4*c+1], t3.y, a3);
            a0 = __fmaf_rn(v[4*c+2], t0.z, a0);
            a1 = __fmaf_rn(v[4*c+2], t1.z, a1);
            a2 = __fmaf_rn(v[4*c+2], t2.z, a2);
            a3 = __fmaf_rn(v[4*c+2], t3.z, a3);
            a0 = __fmaf_rn(v[4*c+3], t0.w, a0);
            a1 = __fmaf_rn(v[4*c+3], t1.w, a1);
            a2 = __fmaf_rn(v[4*c+3], t2.w, a2);
            a3 = __fmaf_rn(v[4*c+3], t3.w, a3);
        }
        float sv[4] = {a0, a1, a2, a3};
#pragma unroll
        for (int d = 0; d < 4; d++) {
            float s = sv[d]; int m = m0 + d;
            if (s > v0)      { v3=v2;i3=i2; v2=v1;i2=i1; v1=v0;i1=i0; v0=s;i0=m; }
            else if (s > v1) { v3=v2;i3=i2; v2=v1;i2=i1; v1=s;i1=m; }
            else if (s > v2) { v3=v2;i3=i2; v2=s;i2=m; }
            else if (s > v3) { v3=s;i3=m; }
        }
    }

    // ---- pass 2: compensated-exact sims for the 4 ranked candidates ----
    int   ci[4] = {i0, i1, i2, i3};
    double ex[4];
#pragma unroll
    for (int t = 0; t < 4; t++) {
        const float* y = ys + ci[t] * C1;
        float s = 0.f, comp = 0.f;
#pragma unroll
        for (int k = 0; k < C1; k++) {
            float a = v[k], bb = y[k];
            float p  = __fmul_rn(a, bb);
            float e  = __fmaf_rn(a, bb, -p);           // exact product tail
            float tt = s + p;
            float z  = (fabsf(s) >= fabsf(p)) ? ((s - tt) + p) : ((p - tt) + s);
            s = tt;
            comp = comp + (z + e);
        }
        ex[t] = (double)s + (double)comp;
    }

    // tie repair: sub-ulp exact gap => jax tie-break (lower index first)
#pragma unroll
    for (int p = 0; p < 3; p++) {
#pragma unroll
        for (int q = 0; q < 3 - p; q++) {
            if (fabs(ex[q] - ex[q+1]) <= EPS_ULP && ci[q] > ci[q+1]) {
                double td = ex[q]; ex[q] = ex[q+1]; ex[q+1] = td;
                int    tm = ci[q]; ci[q] = ci[q+1]; ci[q+1] = tm;
            }
        }
    }

    int* nb = g_nbr + ((size_t)b * NTOK + n) * 3;
    nb[0] = ci[0];   // sample index, consumed by k5_fused via g_T
    nb[1] = ci[1];
    nb[2] = ci[2];
}

// ---------------------------------------------------------------------------
// KT: conv factorization, chip-wide: grid (16 batches, 9 o-chunks of 8).
// T[b][k][m][o] = sum_c w1[o][c][k] * xs[b][m][c].   (11.7us measured)
// ---------------------------------------------------------------------------
#define KT_OC 8
__global__ __launch_bounds__(256) void kT_gemm(const float* __restrict__ w1) {
    __shared__ float w1s[KT_OC * 216];      // 6912 B
    int b   = blockIdx.x;
    int oc0 = blockIdx.y * KT_OC;
    for (int t = threadIdx.x; t < KT_OC * 216 / 4; t += 256)
        ((float4*)w1s)[t] = ((const float4*)(w1 + oc0 * 216))[t];
    __syncthreads();

    int m = threadIdx.x;
    int tok = c_SIDX[m >> 4] * ww + c_SIDX[m & 15];
    float xs[C1];
    {
        const float4* src = (const float4*)(g_x1t + ((size_t)b * NTOK + tok) * C1);
#pragma unroll
        for (int c = 0; c < 18; c++) {
            float4 t = src[c];
            xs[4*c] = t.x; xs[4*c+1] = t.y; xs[4*c+2] = t.z; xs[4*c+3] = t.w;
        }
    }

#pragma unroll
    for (int oo = 0; oo < KT_OC; oo++) {
        int o = oc0 + oo;
        const float4* wrow = (const float4*)(w1s + oo * 216);   // w1[o][c][k]
        float a0 = 0.f, a1 = 0.f, a2 = 0.f;
#pragma unroll
        for (int q = 0; q < 54; q++) {
            float4 wv = wrow[q];
            float we[4] = {wv.x, wv.y, wv.z, wv.w};
#pragma unroll
            for (int e = 0; e < 4; e++) {
                const int idx = 4*q + e;
                const int c = idx / 3, k = idx % 3;
                if (k == 0) a0 = __fmaf_rn(xs[c], we[e], a0);
                if (k == 1) a1 = __fmaf_rn(xs[c], we[e], a1);
                if (k == 2) a2 = __fmaf_rn(xs[c], we[e], a2);
            }
        }
        g_T[(((size_t)b*3 + 0) * MS + m) * C1 + o] = a0;
        g_T[(((size_t)b*3 + 1) * MS + m) * C1 + o] = a1;
        g_T[(((size_t)b*3 + 2) * MS + m) * C1 + o] = a2;
    }
}

// ---------------------------------------------------------------------------
// K5 (fused): sum 3 T rows + bias = conv row, then PixelShuffle + pointwise.
// ---------------------------------------------------------------------------
__global__ __launch_bounds__(256) void k5_fused(const float* __restrict__ b1,
                                                const float* __restrict__ wpw,
                                                const float* __restrict__ bpw,
                                                float* __restrict__ out) {
    __shared__ float ws[16 * 18];
    __shared__ float bs[16];
    __shared__ float b1s[C1];
    int tid = threadIdx.x;
    for (int t = tid; t < 16 * 18; t += 256) ws[t] = wpw[t];
    if (tid < 16) bs[tid] = bpw[tid];
    if (tid < C1) b1s[tid] = b1[tid];
    __syncthreads();

    int idx = blockIdx.x * 256 + tid;   // b*NTOK + n
    int b = idx / NTOK, n = idx % NTOK;
    int i = n / ww, j = n % ww;

    const int* nb = g_nbr + (size_t)idx * 3;
    const float4* t0 = (const float4*)(g_T + (((size_t)b*3 + 0) * MS + nb[0]) * C1);
    const float4* t1 = (const float4*)(g_T + (((size_t)b*3 + 1) * MS + nb[1]) * C1);
    const float4* t2 = (const float4*)(g_T + (((size_t)b*3 + 2) * MS + nb[2]) * C1);

    float row[C1];
#pragma unroll
    for (int c = 0; c < 18; c++) {
        float4 p = t0[c], q = t1[c], r = t2[c];
        row[4*c+0] = b1s[4*c+0] + p.x + q.x + r.x;
        row[4*c+1] = b1s[4*c+1] + p.y + q.y + r.y;
        row[4*c+2] = b1s[4*c+2] + p.z + q.z + r.z;
        row[4*c+3] = b1s[4*c+3] + p.w + q.w + r.w;
    }

    float* ob = out + (size_t)b * CIN * HH * WW;
#pragma unroll 4
    for (int oc = 0; oc < 16; oc++) {
#pragma unroll
        for (int s1 = 0; s1 < 2; s1++) {
            float a0 = bs[oc], a1 = bs[oc];
#pragma unroll
            for (int c = 0; c < 18; c++) {
                float wv = ws[oc * 18 + c];
                a0 = __fmaf_rn(wv, row[c*4 + s1*2 + 0], a0);
                a1 = __fmaf_rn(wv, row[c*4 + s1*2 + 1], a1);
            }
            *(float2*)(ob + ((size_t)oc * HH + (2*i + s1)) * WW + 2*j) = make_float2(a0, a1);
        }
    }
}

// ---------------------------------------------------------------------------
extern "C" void kernel_launch(void* const* d_in, const int* in_sizes, int n_in,
                              void* d_out, int out_size) {
    const float *x = nullptr, *w1 = nullptr, *b1 = nullptr, *wpw = nullptr, *bpw = nullptr;
    for (int i = 0; i < n_in; i++) {
        switch (in_sizes[i]) {
            case 12845056: x   = (const float*)d_in[i]; break;  // (16,16,224,224)
            case 15552:    w1  = (const float*)d_in[i]; break;  // (72,72,3)
            case 72:       b1  = (const float*)d_in[i]; break;  // (72,)
            case 288:      wpw = (const float*)d_in[i]; break;  // (16,18,1,1)
            case 16:       bpw = (const float*)d_in[i]; break;  // (16,)
        }
    }
    float* out = (float*)d_out;

    cudaFuncSetAttribute(k3_sim, cudaFuncAttributeMaxDynamicSharedMemorySize, 73728);

    k1_build   <<<784, 256>>>(x);                        // 16*12544/256
    k2_samples <<<16, 256>>>();
    k3_sim     <<<dim3(49, 16), 256, 73728>>>();         // 12544/256 = 49
    kT_gemm    <<<dim3(16, 9), 256>>>(w1);
    k5_fused   <<<784, 256>>>(b1, wpw, bpw, out);
}

// round 16
// speedup vs baseline: 1.2542x; 1.0753x over previous
#include <cuda_runtime.h>
#include <math.h>

// Problem constants
#define BATCH 16
#define CIN   16
#define HH    224
#define WW    224
#define hh    112
#define ww    112
#define NTOK  12544        // 112*112
#define C1    72           // (16+2)*4
#define CHN   18           // 16+2
#define MS    256          // samples
#define KNB   3

// Scratch (static __device__ -> .bss, no allocations)
__device__ __align__(16) float g_x1t[(size_t)BATCH*NTOK*C1];   // token-major unshuffled input (+coords)
__device__ __align__(16) float g_ys [(size_t)BATCH*MS*C1];     // normalized sample vectors
__device__            int   g_nbr[(size_t)BATCH*NTOK*KNB];     // top-3 neighbor SAMPLE indices (0..255)
__device__ __align__(16) float g_T  [(size_t)BATCH*KNB*MS*C1]; // T[b][k][m][o]: conv-transformed samples

// round(linspace(0,111,16)) — verified against f32 linspace rounding
__constant__ int c_SIDX[16] = {0,7,15,22,30,37,44,52,59,67,74,81,89,96,104,111};

// ---------------------------------------------------------------------------
// K1: coords + pixel-unshuffle into token-major layout.
// ---------------------------------------------------------------------------
__global__ __launch_bounds__(256) void k1_build(const float* __restrict__ x) {
    int idx = blockIdx.x * 256 + threadIdx.x;      // b*NTOK + n, exact grid
    int b = idx / NTOK, n = idx % NTOK;
    int i = n / ww, j = n % ww;
    const float* xb = x + (size_t)b * CIN * HH * WW;
    float row[C1];
#pragma unroll
    for (int ch = 0; ch < CIN; ch++) {
#pragma unroll
        for (int s1 = 0; s1 < 2; s1++) {
            float2 v = *(const float2*)(xb + ((size_t)ch * HH + (2*i + s1)) * WW + 2*j);
            row[ch*4 + s1*2 + 0] = v.x;
            row[ch*4 + s1*2 + 1] = v.y;
        }
    }
#pragma unroll
    for (int s1 = 0; s1 < 2; s1++)
#pragma unroll
        for (int s2 = 0; s2 < 2; s2++) {
            float p = (float)(2*i + s1), q = (float)(2*j + s2);
            float r = sqrtf(__fadd_rn(__fmul_rn(p, p), __fmul_rn(q, q)));  // exact ints
            float rm = fmaxf(r, 1e-12f);
            row[64 + s1*2 + s2] = __fdiv_rn(p, rm);   // channel 16 block
            row[68 + s1*2 + s2] = __fdiv_rn(q, rm);   // channel 17 block
        }
    float4* dst = (float4*)(g_x1t + (size_t)idx * C1);
#pragma unroll
    for (int c = 0; c < C1/4; c++)
        dst[c] = make_float4(row[4*c], row[4*c+1], row[4*c+2], row[4*c+3]);
}

// ---------------------------------------------------------------------------
// K2: gather + L2-normalize the 256 sampled vectors per batch.
// ---------------------------------------------------------------------------
__global__ void k2_samples() {
    int idx = blockIdx.x * blockDim.x + threadIdx.x;   // b*256 + m
    if (idx >= BATCH * MS) return;
    int b = idx >> 8, m = idx & 255;
    int tok = c_SIDX[m >> 4] * ww + c_SIDX[m & 15];
    const float4* src = (const float4*)(g_x1t + ((size_t)b * NTOK + tok) * C1);
    float v[C1];
#pragma unroll
    for (int c = 0; c < 18; c++) {
        float4 t = src[c];
        v[4*c] = t.x; v[4*c+1] = t.y; v[4*c+2] = t.z; v[4*c+3] = t.w;
    }
    float ss = 0.f;
#pragma unroll
    for (int c = 0; c < C1; c++) ss = __fmaf_rn(v[c], v[c], ss);
    float nrm = fmaxf(sqrtf(ss), 1e-12f);
    float4* dst = (float4*)(g_ys + (size_t)idx * C1);
#pragma unroll
    for (int c = 0; c < 18; c++)
        dst[c] = make_float4(__fdiv_rn(v[4*c],   nrm), __fdiv_rn(v[4*c+1], nrm),
                             __fdiv_rn(v[4*c+2], nrm), __fdiv_rn(v[4*c+3], nrm));
}

// ---------------------------------------------------------------------------
// K3: cosine sim + top-3 with sub-ulp tie repair.
// NEW (R16): the expensive compensated pass-2 is GATED. If all adjacent gaps
// in the pass-1 top-4 exceed GAP_SAFE=1e-5, then (chain-vs-exact deviation
// <= ~2e-6 each) every exact gap >= 6e-6 >> EPS_ULP, so the tie repair
// provably cannot swap -> emit pass-1 order directly. Only ~0.1% of tokens
// (including the real sub-ulp ties) take the compensated path. Output is
// bit-identical to the ungated R15 kernel by construction.
// ---------------------------------------------------------------------------
#define EPS_ULP  6.0e-8
#define GAP_SAFE 1.0e-5f
__global__ __launch_bounds__(256) void k3_sim() {
    extern __shared__ float ys[];
    int b = blockIdx.y;
    int n = blockIdx.x * 256 + threadIdx.x;
    {
        const float4* src = (const float4*)(g_ys + (size_t)b * MS * C1);
        float4* d = (float4*)ys;
        for (int t = threadIdx.x; t < MS * C1 / 4; t += 256) d[t] = src[t];
    }
    __syncthreads();

    float v[C1];
    {
        const float4* src = (const float4*)(g_x1t + ((size_t)b * NTOK + n) * C1);
#pragma unroll
        for (int c = 0; c < 18; c++) {
            float4 t = src[c];
            v[4*c] = t.x; v[4*c+1] = t.y; v[4*c+2] = t.z; v[4*c+3] = t.w;
        }
        float ss = 0.f;
#pragma unroll
        for (int c = 0; c < C1; c++) ss = __fmaf_rn(v[c], v[c], ss);
        float nrm = fmaxf(sqrtf(ss), 1e-12f);
#pragma unroll
        for (int c = 0; c < C1; c++) v[c] = __fdiv_rn(v[c], nrm);
    }

    // ---- pass 1: ascending-FMA sims, streaming top-4 ----
    float v0 = -1e30f, v1 = -1e30f, v2 = -1e30f, v3 = -1e30f;
    int   i0 = 0, i1 = 0, i2 = 0, i3 = 0;
    for (int m0 = 0; m0 < MS; m0 += 4) {
        float a0 = 0.f, a1 = 0.f, a2 = 0.f, a3 = 0.f;
        const float* y0 = ys + (m0 + 0) * C1;
        const float* y1 = ys + (m0 + 1) * C1;
        const float* y2 = ys + (m0 + 2) * C1;
        const float* y3 = ys + (m0 + 3) * C1;
#pragma unroll
        for (int c = 0; c < 18; c++) {
            float4 t0 = *(const float4*)(y0 + 4*c);
            float4 t1 = *(const float4*)(y1 + 4*c);
            float4 t2 = *(const float4*)(y2 + 4*c);
            float4 t3 = *(const float4*)(y3 + 4*c);
            a0 = __fmaf_rn(v[4*c],   t0.x, a0);
            a1 = __fmaf_rn(v[4*c],   t1.x, a1);
            a2 = __fmaf_rn(v[4*c],   t2.x, a2);
            a3 = __fmaf_rn(v[4*c],   t3.x, a3);
            a0 = __fmaf_rn(v[4*c+1], t0.y, a0);
            a1 = __fmaf_rn(v[4*c+1], t1.y, a1);
            a2 = __fmaf_rn(v[4*c+1], t2.y, a2);
            a3 = __fmaf_rn(v[4*c+1], t3.y, a3);
            a0 = __fmaf_rn(v[4*c+2], t0.z, a0);
            a1 = __fmaf_rn(v[4*c+2], t1.z, a1);
            a2 = __fmaf_rn(v[4*c+2], t2.z, a2);
            a3 = __fmaf_rn(v[4*c+2], t3.z, a3);
            a0 = __fmaf_rn(v[4*c+3], t0.w, a0);
            a1 = __fmaf_rn(v[4*c+3], t1.w, a1);
            a2 = __fmaf_rn(v[4*c+3], t2.w, a2);
            a3 = __fmaf_rn(v[4*c+3], t3.w, a3);
        }
        float sv[4] = {a0, a1, a2, a3};
#pragma unroll
        for (int d = 0; d < 4; d++) {
            float s = sv[d]; int m = m0 + d;
            if (s > v0)      { v3=v2;i3=i2; v2=v1;i2=i1; v1=v0;i1=i0; v0=s;i0=m; }
            else if (s > v1) { v3=v2;i3=i2; v2=v1;i2=i1; v1=s;i1=m; }
            else if (s > v2) { v3=v2;i3=i2; v2=s;i2=m; }
            else if (s > v3) { v3=s;i3=m; }
        }
    }

    int* nb = g_nbr + ((size_t)b * NTOK + n) * 3;

    // ---- fast path: provably tie-free -> pass-1 order is final ----
    if ((v0 - v1) > GAP_SAFE && (v1 - v2) > GAP_SAFE && (v2 - v3) > GAP_SAFE) {
        nb[0] = i0; nb[1] = i1; nb[2] = i2;
        return;
    }

    // ---- slow path: compensated-exact sims + sub-ulp tie repair ----
    int   ci[4] = {i0, i1, i2, i3};
    double ex[4];
#pragma unroll
    for (int t = 0; t < 4; t++) {
        const float* y = ys + ci[t] * C1;
        float s = 0.f, comp = 0.f;
#pragma unroll
        for (int k = 0; k < C1; k++) {
            float a = v[k], bb = y[k];
            float p  = __fmul_rn(a, bb);
            float e  = __fmaf_rn(a, bb, -p);           // exact product tail
            float tt = s + p;
            float z  = (fabsf(s) >= fabsf(p)) ? ((s - tt) + p) : ((p - tt) + s);
            s = tt;
            comp = comp + (z + e);
        }
        ex[t] = (double)s + (double)comp;
    }
#pragma unroll
    for (int p = 0; p < 3; p++) {
#pragma unroll
        for (int q = 0; q < 3 - p; q++) {
            if (fabs(ex[q] - ex[q+1]) <= EPS_ULP && ci[q] > ci[q+1]) {
                double td = ex[q]; ex[q] = ex[q+1]; ex[q+1] = td;
                int    tm = ci[q]; ci[q] = ci[q+1]; ci[q+1] = tm;
            }
        }
    }
    nb[0] = ci[0];
    nb[1] = ci[1];
    nb[2] = ci[2];
}

// ---------------------------------------------------------------------------
// KT: conv factorization, chip-wide: grid (16 batches, 9 o-chunks of 8).
// T[b][k][m][o] = sum_c w1[o][c][k] * xs[b][m][c].   (10.9us measured)
// ---------------------------------------------------------------------------
#define KT_OC 8
__global__ __launch_bounds__(256) void kT_gemm(const float* __restrict__ w1) {
    __shared__ float w1s[KT_OC * 216];      // 6912 B
    int b   = blockIdx.x;
    int oc0 = blockIdx.y * KT_OC;
    for (int t = threadIdx.x; t < KT_OC * 216 / 4; t += 256)
        ((float4*)w1s)[t] = ((const float4*)(w1 + oc0 * 216))[t];
    __syncthreads();

    int m = threadIdx.x;
    int tok = c_SIDX[m >> 4] * ww + c_SIDX[m & 15];
    float xs[C1];
    {
        const float4* src = (const float4*)(g_x1t + ((size_t)b * NTOK + tok) * C1);
#pragma unroll
        for (int c = 0; c < 18; c++) {
            float4 t = src[c];
            xs[4*c] = t.x; xs[4*c+1] = t.y; xs[4*c+2] = t.z; xs[4*c+3] = t.w;
        }
    }

#pragma unroll
    for (int oo = 0; oo < KT_OC; oo++) {
        int o = oc0 + oo;
        const float4* wrow = (const float4*)(w1s + oo * 216);   // w1[o][c][k]
        float a0 = 0.f, a1 = 0.f, a2 = 0.f;
#pragma unroll
        for (int q = 0; q < 54; q++) {
            float4 wv = wrow[q];
            float we[4] = {wv.x, wv.y, wv.z, wv.w};
#pragma unroll
            for (int e = 0; e < 4; e++) {
                const int idx = 4*q + e;
                const int c = idx / 3, k = idx % 3;
                if (k == 0) a0 = __fmaf_rn(xs[c], we[e], a0);
                if (k == 1) a1 = __fmaf_rn(xs[c], we[e], a1);
                if (k == 2) a2 = __fmaf_rn(xs[c], we[e], a2);
            }
        }
        g_T[(((size_t)b*3 + 0) * MS + m) * C1 + o] = a0;
        g_T[(((size_t)b*3 + 1) * MS + m) * C1 + o] = a1;
        g_T[(((size_t)b*3 + 2) * MS + m) * C1 + o] = a2;
    }
}

// ---------------------------------------------------------------------------
// K5 (fused): sum 3 T rows + bias = conv row, then PixelShuffle + pointwise.
// ---------------------------------------------------------------------------
__global__ __launch_bounds__(256) void k5_fused(const float* __restrict__ b1,
                                                const float* __restrict__ wpw,
                                                const float* __restrict__ bpw,
                                                float* __restrict__ out) {
    __shared__ float ws[16 * 18];
    __shared__ float bs[16];
    __shared__ float b1s[C1];
    int tid = threadIdx.x;
    for (int t = tid; t < 16 * 18; t += 256) ws[t] = wpw[t];
    if (tid < 16) bs[tid] = bpw[tid];
    if (tid < C1) b1s[tid] = b1[tid];
    __syncthreads();

    int idx = blockIdx.x * 256 + tid;   // b*NTOK + n
    int b = idx / NTOK, n = idx % NTOK;
    int i = n / ww, j = n % ww;

    const int* nb = g_nbr + (size_t)idx * 3;
    const float4* t0 = (const float4*)(g_T + (((size_t)b*3 + 0) * MS + nb[0]) * C1);
    const float4* t1 = (const float4*)(g_T + (((size_t)b*3 + 1) * MS + nb[1]) * C1);
    const float4* t2 = (const float4*)(g_T + (((size_t)b*3 + 2) * MS + nb[2]) * C1);

    float row[C1];
#pragma unroll
    for (int c = 0; c < 18; c++) {
        float4 p = t0[c], q = t1[c], r = t2[c];
        row[4*c+0] = b1s[4*c+0] + p.x + q.x + r.x;
        row[4*c+1] = b1s[4*c+1] + p.y + q.y + r.y;
        row[4*c+2] = b1s[4*c+2] + p.z + q.z + r.z;
        row[4*c+3] = b1s[4*c+3] + p.w + q.w + r.w;
    }

    float* ob = out + (size_t)b * CIN * HH * WW;
#pragma unroll 4
    for (int oc = 0; oc < 16; oc++) {
#pragma unroll
        for (int s1 = 0; s1 < 2; s1++) {
            float a0 = bs[oc], a1 = bs[oc];
#pragma unroll
            for (int c = 0; c < 18; c++) {
                float wv = ws[oc * 18 + c];
                a0 = __fmaf_rn(wv, row[c*4 + s1*2 + 0], a0);
                a1 = __fmaf_rn(wv, row[c*4 + s1*2 + 1], a1);
            }
            *(float2*)(ob + ((size_t)oc * HH + (2*i + s1)) * WW + 2*j) = make_float2(a0, a1);
        }
    }
}

// ---------------------------------------------------------------------------
extern "C" void kernel_launch(void* const* d_in, const int* in_sizes, int n_in,
                              void* d_out, int out_size) {
    const float *x = nullptr, *w1 = nullptr, *b1 = nullptr, *wpw = nullptr, *bpw = nullptr;
    for (int i = 0; i < n_in; i++) {
        switch (in_sizes[i]) {
            case 12845056: x   = (const float*)d_in[i]; break;  // (16,16,224,224)
            case 15552:    w1  = (const float*)d_in[i]; break;  // (72,72,3)
            case 72:       b1  = (const float*)d_in[i]; break;  // (72,)
            case 288:      wpw = (const float*)d_in[i]; break;  // (16,18,1,1)
            case 16:       bpw = (const float*)d_in[i]; break;  // (16,)
        }
    }
    float* out = (float*)d_out;

    cudaFuncSetAttribute(k3_sim, cudaFuncAttributeMaxDynamicSharedMemorySize, 73728);

    k1_build   <<<784, 256>>>(x);                        // 16*12544/256
    k2_samples <<<16, 256>>>();
    k3_sim     <<<dim3(49, 16), 256, 73728>>>();         // 12544/256 = 49
    kT_gemm    <<<dim3(16, 9), 256>>>(w1);
    k5_fused   <<<784, 256>>>(b1, wpw, bpw, out);
}